// round 2
// baseline (speedup 1.0000x reference)
#include <cuda_runtime.h>

#define NP 8192
#define NT 8192
#define CAP 256         // max neighbors per node (expected ~41, binomial tail ~70)
#define ROW_F4 (NT/4)   // float4 per adjacency row

// ---------------- static scratch (no allocations allowed) ----------------
__device__ __align__(16) float d_pa[NP * 64];
__device__ __align__(16) float d_pb[NP * 64];
__device__ __align__(16) float d_ta[NT * 64];
__device__ __align__(16) float d_tb[NT * 64];
__device__ int d_rcnt[NP];
__device__ int d_ccnt[NT];
__device__ int d_rlist[NP * CAP];
__device__ int d_clist[NT * CAP];
__device__ float d_logits[NT];

// ---------------- zero the column counters ----------------
__global__ void zero_ccnt_k() {
    int i = blockIdx.x * blockDim.x + threadIdx.x;
    if (i < NT) d_ccnt[i] = 0;
}

// ---------------- single streaming pass over adj: build row/col lists ----------------
__global__ void __launch_bounds__(256) build_k(const float* __restrict__ adj) {
    __shared__ int s_cnt;
    __shared__ int s_list[CAP];
    int row = blockIdx.x;
    if (threadIdx.x == 0) s_cnt = 0;
    __syncthreads();

    const float4* a4 = reinterpret_cast<const float4*>(adj) + (size_t)row * ROW_F4;
    for (int c4 = threadIdx.x; c4 < ROW_F4; c4 += 256) {
        float4 v = __ldcs(&a4[c4]);
        if (v.x != 0.f || v.y != 0.f || v.z != 0.f || v.w != 0.f) {
            int jb = c4 << 2;
            float vals[4] = {v.x, v.y, v.z, v.w};
#pragma unroll
            for (int q = 0; q < 4; q++) {
                if (vals[q] != 0.f) {
                    int j = jb + q;
                    int slot = atomicAdd(&s_cnt, 1);
                    if (slot < CAP) s_list[slot] = j;
                    int cs = atomicAdd(&d_ccnt[j], 1);
                    if (cs < CAP) d_clist[j * CAP + cs] = row;
                }
            }
        }
    }
    __syncthreads();
    int n = min(s_cnt, CAP);
    if (threadIdx.x == 0) d_rcnt[row] = n;
    for (int i = threadIdx.x; i < n; i += 256) d_rlist[row * CAP + i] = s_list[i];
}

// ---------------- fused gather + concat + GEMM + ReLU layer ----------------
// x = SELF_FIRST ? [self, agg(other)] : [agg(other), self];  out = relu(x @ W + B)
template <int INS, int INA, int OUT, bool SELF_FIRST>
__global__ void __launch_bounds__(256) layer_k(
    const float* __restrict__ self_f, const float* __restrict__ other_f,
    const int* __restrict__ cnt, const int* __restrict__ list,
    const float* __restrict__ W, const float* __restrict__ B,
    float* __restrict__ out_f)
{
    constexpr int C = INS + INA;
    constexpr int WARPS = 8;
    __shared__ float sW[C * OUT];
    __shared__ float sB[OUT];
    __shared__ __align__(16) float sX[WARPS][C];

    int tid = threadIdx.x;
    for (int i = tid; i < C * OUT; i += 256) sW[i] = W[i];
    if (tid < OUT) sB[tid] = B[tid];
    __syncthreads();

    int warp = tid >> 5, lane = tid & 31;
    int node = blockIdx.x * WARPS + warp;
    float* xs = sX[warp];

    constexpr int SOFF = SELF_FIRST ? 0 : INA;
    constexpr int AOFF = SELF_FIRST ? INS : 0;

#pragma unroll
    for (int k = lane; k < INS; k += 32) xs[SOFF + k] = self_f[node * INS + k];

    // parallel gather over neighbor list: V lanes per float4-slice, G groups over edges
    constexpr int V = INA / 4;
    constexpr int G = 32 / V;
    int v = lane % V;
    int g = lane / V;
    float4 acc = make_float4(0.f, 0.f, 0.f, 0.f);
    int n = cnt[node];
    const int* lst = list + node * CAP;
    for (int e = g; e < n; e += G) {
        int nbr = lst[e];
        float4 t4 = *reinterpret_cast<const float4*>(other_f + nbr * INA + v * 4);
        acc.x += t4.x; acc.y += t4.y; acc.z += t4.z; acc.w += t4.w;
    }
#pragma unroll
    for (int d = G / 2; d > 0; d >>= 1) {
        acc.x += __shfl_down_sync(0xffffffffu, acc.x, d * V);
        acc.y += __shfl_down_sync(0xffffffffu, acc.y, d * V);
        acc.z += __shfl_down_sync(0xffffffffu, acc.z, d * V);
        acc.w += __shfl_down_sync(0xffffffffu, acc.w, d * V);
    }
    if (g == 0) *reinterpret_cast<float4*>(xs + AOFF + v * 4) = acc;
    __syncwarp();

    // tiny GEMM: each lane owns output columns lane, lane+32
    constexpr int JPL = (OUT + 31) / 32;
    if (lane < OUT) {
        float a[JPL];
#pragma unroll
        for (int jj = 0; jj < JPL; jj++) a[jj] = sB[lane + jj * 32];
#pragma unroll
        for (int k = 0; k < C; k++) {
            float xv = xs[k];
#pragma unroll
            for (int jj = 0; jj < JPL; jj++) a[jj] += xv * sW[k * OUT + lane + jj * 32];
        }
#pragma unroll
        for (int jj = 0; jj < JPL; jj++)
            out_f[node * OUT + lane + jj * 32] = fmaxf(a[jj], 0.f);
    }
}

// ---------------- final logits: x = [adj.T @ p4 (16), t4 (16)] @ w_ac + b_ac ----------------
__global__ void __launch_bounds__(256) logits_k(
    const float* __restrict__ pf, const float* __restrict__ tf,
    const float* __restrict__ w, const float* __restrict__ b)
{
    __shared__ __align__(16) float sx[8][16];
    __shared__ float sw[32];
    __shared__ float sbias;
    int tid = threadIdx.x;
    if (tid < 32) sw[tid] = w[tid];
    if (tid == 0) sbias = b[0];
    __syncthreads();

    int warp = tid >> 5, lane = tid & 31;
    int node = blockIdx.x * 8 + warp;
    int v = lane & 3, g = lane >> 2;  // V=4, G=8 over 16-dim features
    float4 acc = make_float4(0.f, 0.f, 0.f, 0.f);
    int n = d_ccnt[node] < CAP ? d_ccnt[node] : CAP;
    const int* lst = d_clist + node * CAP;
    for (int e = g; e < n; e += 8) {
        int nbr = lst[e];
        float4 t4 = *reinterpret_cast<const float4*>(pf + nbr * 16 + v * 4);
        acc.x += t4.x; acc.y += t4.y; acc.z += t4.z; acc.w += t4.w;
    }
#pragma unroll
    for (int d = 4; d > 0; d >>= 1) {
        acc.x += __shfl_down_sync(0xffffffffu, acc.x, d * 4);
        acc.y += __shfl_down_sync(0xffffffffu, acc.y, d * 4);
        acc.z += __shfl_down_sync(0xffffffffu, acc.z, d * 4);
        acc.w += __shfl_down_sync(0xffffffffu, acc.w, d * 4);
    }
    if (g == 0) *reinterpret_cast<float4*>(&sx[warp][v * 4]) = acc;
    __syncwarp();

    float xval = (lane < 16) ? sx[warp][lane] : tf[node * 16 + (lane - 16)];
    float prod = xval * sw[lane];
#pragma unroll
    for (int d = 16; d > 0; d >>= 1)
        prod += __shfl_down_sync(0xffffffffu, prod, d);
    if (lane == 0) d_logits[node] = prod + sbias;
}

// ---------------- softmax over 8192 logits, single block ----------------
__global__ void __launch_bounds__(1024) softmax_k(float* __restrict__ out) {
    __shared__ float sm[1024];
    int tid = threadIdx.x;
    float m = -1e30f;
    for (int i = tid; i < NT; i += 1024) m = fmaxf(m, d_logits[i]);
    sm[tid] = m; __syncthreads();
    for (int s = 512; s > 0; s >>= 1) {
        if (tid < s) sm[tid] = fmaxf(sm[tid], sm[tid + s]);
        __syncthreads();
    }
    float mx = sm[0];
    __syncthreads();
    float s = 0.f;
    for (int i = tid; i < NT; i += 1024) s += __expf(d_logits[i] - mx);
    sm[tid] = s; __syncthreads();
    for (int st = 512; st > 0; st >>= 1) {
        if (tid < st) sm[tid] += sm[tid + st];
        __syncthreads();
    }
    float inv = 1.f / sm[0];
    for (int i = tid; i < NT; i += 1024) out[i] = __expf(d_logits[i] - mx) * inv;
}

// ---------------- launch ----------------
extern "C" void kernel_launch(void* const* d_in, const int* in_sizes, int n_in,
                              void* d_out, int out_size) {
    const float* p    = (const float*)d_in[0];
    const float* t    = (const float*)d_in[1];
    const float* adj  = (const float*)d_in[2];
    const float* w_p1 = (const float*)d_in[3];  const float* b_p1 = (const float*)d_in[4];
    const float* w_t1 = (const float*)d_in[5];  const float* b_t1 = (const float*)d_in[6];
    const float* w_p2 = (const float*)d_in[7];  const float* b_p2 = (const float*)d_in[8];
    const float* w_t2 = (const float*)d_in[9];  const float* b_t2 = (const float*)d_in[10];
    const float* w_p3 = (const float*)d_in[11]; const float* b_p3 = (const float*)d_in[12];
    const float* w_t3 = (const float*)d_in[13]; const float* b_t3 = (const float*)d_in[14];
    const float* w_p4 = (const float*)d_in[15]; const float* b_p4 = (const float*)d_in[16];
    const float* w_t4 = (const float*)d_in[17]; const float* b_t4 = (const float*)d_in[18];
    const float* w_ac = (const float*)d_in[19]; const float* b_ac = (const float*)d_in[20];
    float* out = (float*)d_out;

    float *pa, *pb, *ta, *tb;
    int *rcnt, *ccnt, *rlist, *clist;
    cudaGetSymbolAddress((void**)&pa, d_pa);
    cudaGetSymbolAddress((void**)&pb, d_pb);
    cudaGetSymbolAddress((void**)&ta, d_ta);
    cudaGetSymbolAddress((void**)&tb, d_tb);
    cudaGetSymbolAddress((void**)&rcnt, d_rcnt);
    cudaGetSymbolAddress((void**)&ccnt, d_ccnt);
    cudaGetSymbolAddress((void**)&rlist, d_rlist);
    cudaGetSymbolAddress((void**)&clist, d_clist);

    zero_ccnt_k<<<32, 256>>>();
    build_k<<<NP, 256>>>(adj);

    // L1: in (8,8) -> out (8,8)
    layer_k<8, 8, 8, true ><<<NP / 8, 256>>>(p,  t,  rcnt, rlist, w_p1, b_p1, pa);
    layer_k<8, 8, 8, false><<<NT / 8, 256>>>(t,  p,  ccnt, clist, w_t1, b_t1, ta);
    // L2: in (8,8) -> out (16,16)
    layer_k<8, 8, 16, true ><<<NP / 8, 256>>>(pa, ta, rcnt, rlist, w_p2, b_p2, pb);
    layer_k<8, 8, 16, false><<<NT / 8, 256>>>(ta, pa, ccnt, clist, w_t2, b_t2, tb);
    // L3: in (16,16) -> out (64,64)
    layer_k<16, 16, 64, true ><<<NP / 8, 256>>>(pb, tb, rcnt, rlist, w_p3, b_p3, pa);
    layer_k<16, 16, 64, false><<<NT / 8, 256>>>(tb, pb, ccnt, clist, w_t3, b_t3, ta);
    // L4: in (64,64) -> out (16,16)
    layer_k<64, 64, 16, true ><<<NP / 8, 256>>>(pa, ta, rcnt, rlist, w_p4, b_p4, pb);
    layer_k<64, 64, 16, false><<<NT / 8, 256>>>(ta, pa, ccnt, clist, w_t4, b_t4, tb);

    logits_k<<<NT / 8, 256>>>(pb, tb, w_ac, b_ac);
    softmax_k<<<1, 1024>>>(out);
}